// round 13
// baseline (speedup 1.0000x reference)
#include <cuda_runtime.h>
#include <cstdint>
#include <math.h>

#define BATCH 8
#define TLEN  2048
#define DIM   1024
#define HID   4096
#define BT    (BATCH*TLEN)

// ---------------- scratch (device globals; allocation-free) ----------------
__device__ float g_xn  [(size_t)BT*DIM];
__device__ float g_qkv [(size_t)BT*3*DIM];
__device__ float g_vT  [(size_t)BT*DIM];
__device__ float g_sc  [(size_t)BATCH*TLEN*TLEN];
__device__ float g_attn[(size_t)BT*DIM];
__device__ float g_x1  [(size_t)BT*DIM];
__device__ float g_h   [(size_t)BT*DIM];
__device__ float g_h1  [(size_t)BT*HID];
__device__ float g_wqkvT[(size_t)3*DIM*DIM];
__device__ float g_bqkv [(size_t)3*DIM];
__device__ float g_woT [(size_t)DIM*DIM];
__device__ float g_w1T [(size_t)DIM*HID];
__device__ float g_w2T [(size_t)DIM*HID];

// ---------------- helpers ----------------
__device__ __forceinline__ uint32_t smem_u32(const void* p) {
    uint32_t a;
    asm("{ .reg .u64 t; cvta.to.shared.u64 t, %1; cvt.u32.u64 %0, t; }" : "=r"(a) : "l"(p));
    return a;
}
__device__ __forceinline__ float to_tf32(float x) {
    uint32_t u;
    asm("cvt.rna.tf32.f32 %0, %1;" : "=r"(u) : "f"(x));
    return __uint_as_float(u);
}
#define CPA(dst, src) \
    asm volatile("cp.async.cg.shared.global [%0], [%1], 16;" :: "r"(dst), "l"(src) : "memory")
#define CPA_COMMIT() asm volatile("cp.async.commit_group;" ::: "memory")
#define CPA_WAIT1()  asm volatile("cp.async.wait_group 1;" ::: "memory")

__device__ __forceinline__ void mma_tf32(float* d, const uint32_t* a, const uint32_t* b) {
    asm volatile(
        "mma.sync.aligned.m16n8k8.row.col.f32.tf32.tf32.f32 "
        "{%0,%1,%2,%3}, {%4,%5,%6,%7}, {%8,%9}, {%0,%1,%2,%3};"
        : "+f"(d[0]), "+f"(d[1]), "+f"(d[2]), "+f"(d[3])
        : "r"(a[0]), "r"(a[1]), "r"(a[2]), "r"(a[3]), "r"(b[0]), "r"(b[1]));
}

// ---------------- tf32 MMA GEMM: C = alpha*(A @ B^T) [+bias] [gelu] [+res] ----
// A: [M x K] row-major (ld=lda). B: [N x K] row-major (ld=ldb). CTA tile 128x128,
// 128 threads, 4 warps (2x2), warp tile 64x64, BK=32, 3-stage cp.async pipeline.
// flags: 1 = skip tiles bn>bm (causal scores), 2 = clamp K to (bm+1)*128 (PV).
#define SROW 36
#define STAGE_F (128 * SROW)
#define NSTAGE 3
#define SMEM_BYTES (NSTAGE * 2 * STAGE_F * 4)

template<bool GELU, bool CVT>
__global__ void __launch_bounds__(128, 2) mma_gemm(
    const float* __restrict__ A, const float* __restrict__ B, float* __restrict__ C,
    int K, int lda, int ldb, int ldc,
    long sA, long sB, long sC,
    float alpha, const float* __restrict__ bias, const float* __restrict__ res,
    int flags)
{
    int bn = blockIdx.x, bm = blockIdx.y, bz = blockIdx.z;
    if ((flags & 1) && bn > bm) return;
    int Keff = (flags & 2) ? min(K, (bm + 1) * 128) : K;

    extern __shared__ float smf[];
    float* As = smf;
    float* Bs = smf + NSTAGE * STAGE_F;
    uint32_t asb = smem_u32(As), bsb = smem_u32(Bs);

    int tid = threadIdx.x;
    int lane = tid & 31, warp = tid >> 5;
    int wm = warp & 1, wn = warp >> 1;
    int m0 = wm * 64, n0 = wn * 64;
    int lq = lane >> 2, lr = lane & 3;

    const float* Ab = A + (long)bz * sA + (long)bm * 128 * lda;
    const float* Bb = B + (long)bz * sB + (long)bn * 128 * ldb;

    int lc = (tid & 7) * 4;   // float offset of 16B chunk within 32-float k-slab
    int mr = tid >> 3;        // 0..15

    float acc[4][8][4];
    #pragma unroll
    for (int mt = 0; mt < 4; mt++)
        #pragma unroll
        for (int nt = 0; nt < 8; nt++)
            #pragma unroll
            for (int r = 0; r < 4; r++) acc[mt][nt][r] = 0.f;

    int nk = Keff >> 5;

    // ---- loads for one stage (16 cp.async per thread) ----
    #define LOAD_STAGE(st, k0)                                                    \
        {                                                                         \
            _Pragma("unroll")                                                     \
            for (int i = 0; i < 8; i++) {                                         \
                int m = mr + i * 16;                                              \
                uint32_t da = asb + (uint32_t)(((st) * 128 + m) * SROW + lc) * 4; \
                uint32_t db = bsb + (uint32_t)(((st) * 128 + m) * SROW + lc) * 4; \
                CPA(da, Ab + (long)m * lda + (k0) + lc);                          \
                CPA(db, Bb + (long)m * ldb + (k0) + lc);                          \
            }                                                                     \
            CPA_COMMIT();                                                         \
        }

    LOAD_STAGE(0, 0)
    LOAD_STAGE(1, 32)

    for (int i = 0; i < nk; i++) {
        int s = i % NSTAGE;
        CPA_WAIT1();
        __syncthreads();

        // prefetch stage i+2 (buffer (i+2)%3 was consumed in iter i-1)
        if (i + 2 < nk) {
            int s2 = (i + 2) % NSTAGE;
            int k0 = (i + 2) * 32;
            LOAD_STAGE(s2, k0)
        } else {
            CPA_COMMIT();
        }

        const float* Ash = As + s * STAGE_F;
        const float* Bsh = Bs + s * STAGE_F;
        #pragma unroll
        for (int ks = 0; ks < 4; ks++) {
            int kk = ks * 8 + lr;
            uint32_t a[4][4];
            #pragma unroll
            for (int mt = 0; mt < 4; mt++) {
                const float* p = Ash + (m0 + mt * 16 + lq) * SROW + kk;
                a[mt][0] = __float_as_uint(p[0]);
                a[mt][1] = __float_as_uint(p[8 * SROW]);
                a[mt][2] = __float_as_uint(p[4]);
                a[mt][3] = __float_as_uint(p[8 * SROW + 4]);
            }
            #pragma unroll
            for (int nt = 0; nt < 8; nt++) {
                const float* pb = Bsh + (n0 + nt * 8 + lq) * SROW + kk;
                uint32_t b[2];
                b[0] = __float_as_uint(pb[0]);
                b[1] = __float_as_uint(pb[4]);
                #pragma unroll
                for (int mt = 0; mt < 4; mt++)
                    mma_tf32(acc[mt][nt], a[mt], b);
            }
        }
        __syncthreads();
    }

    // ---- epilogue ----
    #pragma unroll
    for (int mt = 0; mt < 4; mt++) {
        int r1 = bm * 128 + m0 + mt * 16 + lq;
        #pragma unroll
        for (int half = 0; half < 2; half++) {
            int r = r1 + half * 8;
            float* Cp = C + (long)bz * sC + (long)r * ldc + bn * 128;
            const float* Rp = res ? (res + (long)bz * sC + (long)r * ldc + bn * 128) : nullptr;
            #pragma unroll
            for (int nt = 0; nt < 8; nt++) {
                int cc = n0 + nt * 8 + lr * 2;
                float2 o;
                #pragma unroll
                for (int j = 0; j < 2; j++) {
                    float val = alpha * acc[mt][nt][half * 2 + j];
                    if (bias) val += __ldg(&bias[bn * 128 + cc + j]);
                    if (GELU) val = 0.5f * val * (1.f + erff(val * 0.70710678118654752f));
                    if (Rp)   val += Rp[cc + j];
                    if (CVT)  val = to_tf32(val);
                    (&o.x)[j] = val;
                }
                *(float2*)(Cp + cc) = o;
            }
        }
    }
}

// ---------------- transpose (+ tf32 cvt): dst[c][r] = src[r][c] ----------------
// src rows have leading dim lds; dst rows have leading dim R.
__global__ void transpose_kernel(const float* __restrict__ src, float* __restrict__ dst,
                                 int R, int C, int lds, long sS, long sD) {
    __shared__ float t[32][33];
    int c0 = blockIdx.x * 32, r0 = blockIdx.y * 32;
    const float* s = src + (long)blockIdx.z * sS;
    float* d = dst + (long)blockIdx.z * sD;
    int x = threadIdx.x, y = threadIdx.y;
    #pragma unroll
    for (int i = 0; i < 32; i += 8) t[y + i][x] = s[(long)(r0 + y + i) * lds + c0 + x];
    __syncthreads();
    #pragma unroll
    for (int i = 0; i < 32; i += 8) d[(long)(c0 + y + i) * R + r0 + x] = to_tf32(t[x][y + i]);
}

// ---------------- bias concat ----------------
__global__ void concat3_kernel(const float* __restrict__ a, const float* __restrict__ b,
                               const float* __restrict__ c, float* __restrict__ o) {
    int i = blockIdx.x * 256 + threadIdx.x;
    if (i < DIM)            o[i] = a[i];
    else if (i < 2 * DIM)   o[i] = b[i - DIM];
    else if (i < 3 * DIM)   o[i] = c[i - 2 * DIM];
}

// ---------------- RMSNorm (+ tf32 cvt on output) ----------------
__global__ void rmsnorm_kernel(const float* __restrict__ x,
                               const float* __restrict__ w,
                               float* __restrict__ o) {
    int row = blockIdx.x;
    int tid = threadIdx.x;
    const float4* xr = (const float4*)(x + (size_t)row * DIM);
    float4 v = xr[tid];
    float ss = v.x*v.x + v.y*v.y + v.z*v.z + v.w*v.w;
    #pragma unroll
    for (int off = 16; off; off >>= 1) ss += __shfl_xor_sync(~0u, ss, off);
    __shared__ float red[8];
    if ((tid & 31) == 0) red[tid >> 5] = ss;
    __syncthreads();
    float tot = 0.f;
    #pragma unroll
    for (int i = 0; i < 8; i++) tot += red[i];
    float inv = rsqrtf(tot * (1.0f/DIM) + 1e-6f);
    float4 w4 = ((const float4*)w)[tid];
    float4 r;
    r.x = to_tf32(v.x * inv * w4.x); r.y = to_tf32(v.y * inv * w4.y);
    r.z = to_tf32(v.z * inv * w4.z); r.w = to_tf32(v.w * inv * w4.w);
    ((float4*)(o + (size_t)row * DIM))[tid] = r;
}

// ---------------- causal softmax (in-place, + tf32 cvt on probs) ----------------
__global__ void softmax_causal_kernel(float* __restrict__ s) {
    int t = blockIdx.x;
    int b = blockIdx.y;
    float* row = s + ((size_t)b * TLEN + t) * TLEN;
    int tid = threadIdx.x;
    int nvalid = t + 1;
    float vals[8];
    float mx = -3.0e38f;
    #pragma unroll
    for (int i = 0; i < 8; i++) {
        int idx = tid + i * 256;
        vals[i] = (idx < nvalid) ? row[idx] : -3.0e38f;
        mx = fmaxf(mx, vals[i]);
    }
    __shared__ float red[8];
    #pragma unroll
    for (int off = 16; off; off >>= 1) mx = fmaxf(mx, __shfl_xor_sync(~0u, mx, off));
    if ((tid & 31) == 0) red[tid >> 5] = mx;
    __syncthreads();
    mx = -3.0e38f;
    #pragma unroll
    for (int i = 0; i < 8; i++) mx = fmaxf(mx, red[i]);

    float sum = 0.f;
    #pragma unroll
    for (int i = 0; i < 8; i++) {
        int idx = tid + i * 256;
        vals[i] = (idx < nvalid) ? __expf(vals[i] - mx) : 0.f;
        sum += vals[i];
    }
    #pragma unroll
    for (int off = 16; off; off >>= 1) sum += __shfl_xor_sync(~0u, sum, off);
    __syncthreads();
    if ((tid & 31) == 0) red[tid >> 5] = sum;
    __syncthreads();
    float tot = 0.f;
    #pragma unroll
    for (int i = 0; i < 8; i++) tot += red[i];
    float inv = 1.0f / tot;
    #pragma unroll
    for (int i = 0; i < 8; i++) {
        int idx = tid + i * 256;
        row[idx] = to_tf32(vals[i] * inv);
    }
}

// ---------------- launch ----------------
extern "C" void kernel_launch(void* const* d_in, const int* in_sizes, int n_in,
                              void* d_out, int out_size) {
    const float* x   = (const float*)d_in[0];
    const float* anw = (const float*)d_in[1];
    const float* mnw = (const float*)d_in[2];
    const float* wq  = (const float*)d_in[3];
    const float* bq  = (const float*)d_in[4];
    const float* wk  = (const float*)d_in[5];
    const float* bk  = (const float*)d_in[6];
    const float* wv  = (const float*)d_in[7];
    const float* bv  = (const float*)d_in[8];
    const float* wo  = (const float*)d_in[9];
    const float* bo  = (const float*)d_in[10];
    const float* w1  = (const float*)d_in[11];
    const float* b1  = (const float*)d_in[12];
    const float* w2  = (const float*)d_in[13];
    const float* b2  = (const float*)d_in[14];
    float* out = (float*)d_out;

    float *xn, *qkv, *vT, *sc, *attn, *x1, *h, *h1;
    float *wqkvT, *bqkv, *woT, *w1T, *w2T;
    cudaGetSymbolAddress((void**)&xn,    g_xn);
    cudaGetSymbolAddress((void**)&qkv,   g_qkv);
    cudaGetSymbolAddress((void**)&vT,    g_vT);
    cudaGetSymbolAddress((void**)&sc,    g_sc);
    cudaGetSymbolAddress((void**)&attn,  g_attn);
    cudaGetSymbolAddress((void**)&x1,    g_x1);
    cudaGetSymbolAddress((void**)&h,     g_h);
    cudaGetSymbolAddress((void**)&h1,    g_h1);
    cudaGetSymbolAddress((void**)&wqkvT, g_wqkvT);
    cudaGetSymbolAddress((void**)&bqkv,  g_bqkv);
    cudaGetSymbolAddress((void**)&woT,   g_woT);
    cudaGetSymbolAddress((void**)&w1T,   g_w1T);
    cudaGetSymbolAddress((void**)&w2T,   g_w2T);

    cudaFuncSetAttribute(mma_gemm<false,false>, cudaFuncAttributeMaxDynamicSharedMemorySize, SMEM_BYTES);
    cudaFuncSetAttribute(mma_gemm<false,true>,  cudaFuncAttributeMaxDynamicSharedMemorySize, SMEM_BYTES);
    cudaFuncSetAttribute(mma_gemm<true,true>,   cudaFuncAttributeMaxDynamicSharedMemorySize, SMEM_BYTES);

    const long TD  = (long)TLEN * DIM;
    const long T3D = (long)TLEN * 3 * DIM;
    const long TT  = (long)TLEN * TLEN;
    dim3 tb(32, 8);

    // weight transposes (convert to tf32); wq/wk/wv land in one [3072 x 1024] buffer
    transpose_kernel<<<dim3(32, 32), tb>>>(wq, wqkvT,               DIM, DIM, DIM, 0, 0);
    transpose_kernel<<<dim3(32, 32), tb>>>(wk, wqkvT + DIM*DIM,     DIM, DIM, DIM, 0, 0);
    transpose_kernel<<<dim3(32, 32), tb>>>(wv, wqkvT + 2*DIM*DIM,   DIM, DIM, DIM, 0, 0);
    transpose_kernel<<<dim3(32, 32), tb>>>(wo, woT, DIM, DIM, DIM, 0, 0);
    transpose_kernel<<<dim3(128, 32), tb>>>(w1, w1T, DIM, HID, HID, 0, 0);
    transpose_kernel<<<dim3(32, 128), tb>>>(w2, w2T, HID, DIM, DIM, 0, 0);
    concat3_kernel<<<12, 256>>>(bq, bk, bv, bqkv);

    // 1) xn = rmsnorm(x) (tf32)
    rmsnorm_kernel<<<BT, 256>>>(x, anw, xn);

    // 2) qkv = xn @ [wq|wk|wv]^T + bqkv   (M=16384, N=3072, K=1024; tf32 out)
    dim3 gQKV(3 * DIM / 128, BT / 128, 1);
    mma_gemm<false,true><<<gQKV, 128, SMEM_BYTES>>>(xn, wqkvT, qkv, DIM, DIM, DIM, 3*DIM,
                                                    0, 0, 0, 1.f, bqkv, nullptr, 0);
    const float* q = qkv;
    const float* k = qkv + DIM;
    const float* v = qkv + 2 * DIM;

    // v^T per batch: [T,D] (ld 3072) -> [D,T] (tf32)
    transpose_kernel<<<dim3(DIM / 32, TLEN / 32, BATCH), tb>>>(v, vT, TLEN, DIM, 3*DIM, T3D, TD);

    // 3) scores = q @ k^T / 32, causal tiles only
    dim3 gSC(TLEN / 128, TLEN / 128, BATCH);
    mma_gemm<false,false><<<gSC, 128, SMEM_BYTES>>>(q, k, sc, DIM, 3*DIM, 3*DIM, TLEN,
                                                    T3D, T3D, TT, 0.03125f, nullptr, nullptr, 1);

    // 4) causal softmax (probs emitted as tf32)
    softmax_causal_kernel<<<dim3(TLEN, BATCH), 256>>>(sc);

    // 5) attn = probs @ v  (B = vT, K clamped causally; attn emitted tf32)
    dim3 gPV(DIM / 128, TLEN / 128, BATCH);
    mma_gemm<false,true><<<gPV, 128, SMEM_BYTES>>>(sc, vT, attn, TLEN, TLEN, TLEN, DIM,
                                                   TT, TD, TD, 1.f, nullptr, nullptr, 2);

    // 6) x1 = x + attn @ wo^T + bo   (fp32 out)
    dim3 gO(DIM / 128, BT / 128, 1);
    mma_gemm<false,false><<<gO, 128, SMEM_BYTES>>>(attn, woT, x1, DIM, DIM, DIM, DIM,
                                                   0, 0, 0, 1.f, bo, x, 0);

    // 7) h = rmsnorm(x1) (tf32)
    rmsnorm_kernel<<<BT, 256>>>(x1, mnw, h);

    // 8) h1 = gelu(h @ w1^T + b1) (tf32 out)
    dim3 gUP(HID / 128, BT / 128, 1);
    mma_gemm<true,true><<<gUP, 128, SMEM_BYTES>>>(h, w1T, h1, DIM, DIM, DIM, HID,
                                                  0, 0, 0, 1.f, b1, nullptr, 0);

    // 9) out = x1 + h1 @ w2^T + b2 (fp32 out)
    dim3 gDN(DIM / 128, BT / 128, 1);
    mma_gemm<false,false><<<gDN, 128, SMEM_BYTES>>>(h1, w2T, out, HID, HID, HID, DIM,
                                                    0, 0, 0, 1.f, b2, x1, 0);
}

// round 15
// speedup vs baseline: 1.5122x; 1.5122x over previous
#include <cuda_runtime.h>
#include <cstdint>
#include <math.h>

#define BATCH 8
#define TLEN  2048
#define DIM   1024
#define HID   4096
#define BT    (BATCH*TLEN)

// ---------------- scratch (device globals; allocation-free) ----------------
__device__ float g_xn  [(size_t)BT*DIM];
__device__ float g_qkv [(size_t)BT*3*DIM];
__device__ float g_vT  [(size_t)BT*DIM];
__device__ float g_sc  [(size_t)BATCH*TLEN*TLEN];
__device__ float g_attn[(size_t)BT*DIM];
__device__ float g_x1  [(size_t)BT*DIM];
__device__ float g_h   [(size_t)BT*DIM];
__device__ float g_h1  [(size_t)BT*HID];
__device__ float g_wqkvT[(size_t)3*DIM*DIM];
__device__ float g_bqkv [(size_t)3*DIM];
__device__ float g_woT [(size_t)DIM*DIM];
__device__ float g_w1T [(size_t)DIM*HID];
__device__ float g_w2T [(size_t)DIM*HID];

// ---------------- helpers ----------------
__device__ __forceinline__ uint32_t smem_u32(const void* p) {
    uint32_t a;
    asm("{ .reg .u64 t; cvta.to.shared.u64 t, %1; cvt.u32.u64 %0, t; }" : "=r"(a) : "l"(p));
    return a;
}
__device__ __forceinline__ float to_tf32(float x) {
    uint32_t u;
    asm("cvt.rna.tf32.f32 %0, %1;" : "=r"(u) : "f"(x));
    return __uint_as_float(u);
}
#define CPA(dst, src) \
    asm volatile("cp.async.cg.shared.global [%0], [%1], 16;" :: "r"(dst), "l"(src) : "memory")
#define CPA_COMMIT() asm volatile("cp.async.commit_group;" ::: "memory")
#define CPA_WAIT1()  asm volatile("cp.async.wait_group 1;" ::: "memory")

__device__ __forceinline__ void mma_tf32(float* d, const uint32_t* a, const uint32_t* b) {
    asm volatile(
        "mma.sync.aligned.m16n8k8.row.col.f32.tf32.tf32.f32 "
        "{%0,%1,%2,%3}, {%4,%5,%6,%7}, {%8,%9}, {%0,%1,%2,%3};"
        : "+f"(d[0]), "+f"(d[1]), "+f"(d[2]), "+f"(d[3])
        : "r"(a[0]), "r"(a[1]), "r"(a[2]), "r"(a[3]), "r"(b[0]), "r"(b[1]));
}

// ---------------- tf32 MMA GEMM: C = alpha*(A @ B^T) [+bias] [gelu] [+res] ----
// A: [M x K] row-major (ld=lda). B: [N x K] row-major (ld=ldb). CTA tile 128x128,
// 256 threads, 8 warps (4Mx2N), warp tile 32x64, BK=32, 3-stage cp.async pipeline.
// (R4 warp shape — 16 warps/SM — restored after R5's 64x64/8-warp regression.)
// flags: 1 = skip tiles bn>bm (causal scores), 2 = clamp K to (bm+1)*128 (PV).
#define SROW 36
#define STAGE_F (128 * SROW)
#define NSTAGE 3
#define SMEM_BYTES (NSTAGE * 2 * STAGE_F * 4)

template<bool GELU, bool CVT>
__global__ void __launch_bounds__(256, 2) mma_gemm(
    const float* __restrict__ A, const float* __restrict__ B, float* __restrict__ C,
    int K, int lda, int ldb, int ldc,
    long sA, long sB, long sC,
    float alpha, const float* __restrict__ bias, const float* __restrict__ res,
    int flags)
{
    int bn = blockIdx.x, bm = blockIdx.y, bz = blockIdx.z;
    if ((flags & 1) && bn > bm) return;
    int Keff = (flags & 2) ? min(K, (bm + 1) * 128) : K;

    extern __shared__ float smf[];
    float* As = smf;
    float* Bs = smf + NSTAGE * STAGE_F;
    uint32_t asb = smem_u32(As), bsb = smem_u32(Bs);

    int tid = threadIdx.x;
    int lane = tid & 31, warp = tid >> 5;
    int wm = warp & 3, wn = warp >> 2;
    int m0 = wm * 32, n0 = wn * 64;
    int lq = lane >> 2, lr = lane & 3;

    const float* Ab = A + (long)bz * sA + (long)bm * 128 * lda;
    const float* Bb = B + (long)bz * sB + (long)bn * 128 * ldb;

    int lc = (tid & 7) * 4;   // float offset of 16B chunk within 32-float k-slab
    int mr = tid >> 3;        // 0..31

    float acc[2][8][4];
    #pragma unroll
    for (int mt = 0; mt < 2; mt++)
        #pragma unroll
        for (int nt = 0; nt < 8; nt++)
            #pragma unroll
            for (int r = 0; r < 4; r++) acc[mt][nt][r] = 0.f;

    int nk = Keff >> 5;

    // ---- loads for one stage (8 cp.async per thread, 256 threads) ----
    #define LOAD_STAGE(st, k0)                                                    \
        {                                                                         \
            _Pragma("unroll")                                                     \
            for (int i = 0; i < 4; i++) {                                         \
                int m = mr + i * 32;                                              \
                uint32_t da = asb + (uint32_t)(((st) * 128 + m) * SROW + lc) * 4; \
                uint32_t db = bsb + (uint32_t)(((st) * 128 + m) * SROW + lc) * 4; \
                CPA(da, Ab + (long)m * lda + (k0) + lc);                          \
                CPA(db, Bb + (long)m * ldb + (k0) + lc);                          \
            }                                                                     \
            CPA_COMMIT();                                                         \
        }

    LOAD_STAGE(0, 0)
    LOAD_STAGE(1, 32)

    for (int i = 0; i < nk; i++) {
        int s = i % NSTAGE;
        CPA_WAIT1();
        __syncthreads();

        // prefetch stage i+2 into buffer (i+2)%3 (its readers synced in iter i-1)
        if (i + 2 < nk) {
            int s2 = (i + 2) % NSTAGE;
            int k0 = (i + 2) * 32;
            LOAD_STAGE(s2, k0)
        } else {
            CPA_COMMIT();
        }

        const float* Ash = As + s * STAGE_F;
        const float* Bsh = Bs + s * STAGE_F;
        #pragma unroll
        for (int ks = 0; ks < 4; ks++) {
            int kk = ks * 8 + lr;
            uint32_t a[2][4];
            #pragma unroll
            for (int mt = 0; mt < 2; mt++) {
                const float* p = Ash + (m0 + mt * 16 + lq) * SROW + kk;
                a[mt][0] = __float_as_uint(p[0]);
                a[mt][1] = __float_as_uint(p[8 * SROW]);
                a[mt][2] = __float_as_uint(p[4]);
                a[mt][3] = __float_as_uint(p[8 * SROW + 4]);
            }
            #pragma unroll
            for (int nt = 0; nt < 8; nt++) {
                const float* pb = Bsh + (n0 + nt * 8 + lq) * SROW + kk;
                uint32_t b[2];
                b[0] = __float_as_uint(pb[0]);
                b[1] = __float_as_uint(pb[4]);
                #pragma unroll
                for (int mt = 0; mt < 2; mt++)
                    mma_tf32(acc[mt][nt], a[mt], b);
            }
        }
        __syncthreads();
    }

    // ---- epilogue ----
    #pragma unroll
    for (int mt = 0; mt < 2; mt++) {
        int r1 = bm * 128 + m0 + mt * 16 + lq;
        #pragma unroll
        for (int half = 0; half < 2; half++) {
            int r = r1 + half * 8;
            float* Cp = C + (long)bz * sC + (long)r * ldc + bn * 128;
            const float* Rp = res ? (res + (long)bz * sC + (long)r * ldc + bn * 128) : nullptr;
            #pragma unroll
            for (int nt = 0; nt < 8; nt++) {
                int cc = n0 + nt * 8 + lr * 2;
                float2 o;
                #pragma unroll
                for (int j = 0; j < 2; j++) {
                    float val = alpha * acc[mt][nt][half * 2 + j];
                    if (bias) val += __ldg(&bias[bn * 128 + cc + j]);
                    if (GELU) val = 0.5f * val * (1.f + erff(val * 0.70710678118654752f));
                    if (Rp)   val += Rp[cc + j];
                    if (CVT)  val = to_tf32(val);
                    (&o.x)[j] = val;
                }
                *(float2*)(Cp + cc) = o;
            }
        }
    }
}

// ---------------- transpose (+ tf32 cvt): dst[c][r] = src[r][c] ----------------
// src rows have leading dim lds; dst rows have leading dim R.
__global__ void transpose_kernel(const float* __restrict__ src, float* __restrict__ dst,
                                 int R, int C, int lds, long sS, long sD) {
    __shared__ float t[32][33];
    int c0 = blockIdx.x * 32, r0 = blockIdx.y * 32;
    const float* s = src + (long)blockIdx.z * sS;
    float* d = dst + (long)blockIdx.z * sD;
    int x = threadIdx.x, y = threadIdx.y;
    #pragma unroll
    for (int i = 0; i < 32; i += 8) t[y + i][x] = s[(long)(r0 + y + i) * lds + c0 + x];
    __syncthreads();
    #pragma unroll
    for (int i = 0; i < 32; i += 8) d[(long)(c0 + y + i) * R + r0 + x] = to_tf32(t[x][y + i]);
}

// ---------------- bias concat ----------------
__global__ void concat3_kernel(const float* __restrict__ a, const float* __restrict__ b,
                               const float* __restrict__ c, float* __restrict__ o) {
    int i = blockIdx.x * 256 + threadIdx.x;
    if (i < DIM)            o[i] = a[i];
    else if (i < 2 * DIM)   o[i] = b[i - DIM];
    else if (i < 3 * DIM)   o[i] = c[i - 2 * DIM];
}

// ---------------- RMSNorm (+ tf32 cvt on output) ----------------
__global__ void rmsnorm_kernel(const float* __restrict__ x,
                               const float* __restrict__ w,
                               float* __restrict__ o) {
    int row = blockIdx.x;
    int tid = threadIdx.x;
    const float4* xr = (const float4*)(x + (size_t)row * DIM);
    float4 v = xr[tid];
    float ss = v.x*v.x + v.y*v.y + v.z*v.z + v.w*v.w;
    #pragma unroll
    for (int off = 16; off; off >>= 1) ss += __shfl_xor_sync(~0u, ss, off);
    __shared__ float red[8];
    if ((tid & 31) == 0) red[tid >> 5] = ss;
    __syncthreads();
    float tot = 0.f;
    #pragma unroll
    for (int i = 0; i < 8; i++) tot += red[i];
    float inv = rsqrtf(tot * (1.0f/DIM) + 1e-6f);
    float4 w4 = ((const float4*)w)[tid];
    float4 r;
    r.x = to_tf32(v.x * inv * w4.x); r.y = to_tf32(v.y * inv * w4.y);
    r.z = to_tf32(v.z * inv * w4.z); r.w = to_tf32(v.w * inv * w4.w);
    ((float4*)(o + (size_t)row * DIM))[tid] = r;
}

// ---------------- causal softmax (in-place, + tf32 cvt on probs) ----------------
__global__ void softmax_causal_kernel(float* __restrict__ s) {
    int t = blockIdx.x;
    int b = blockIdx.y;
    float* row = s + ((size_t)b * TLEN + t) * TLEN;
    int tid = threadIdx.x;
    int nvalid = t + 1;
    float vals[8];
    float mx = -3.0e38f;
    #pragma unroll
    for (int i = 0; i < 8; i++) {
        int idx = tid + i * 256;
        vals[i] = (idx < nvalid) ? row[idx] : -3.0e38f;
        mx = fmaxf(mx, vals[i]);
    }
    __shared__ float red[8];
    #pragma unroll
    for (int off = 16; off; off >>= 1) mx = fmaxf(mx, __shfl_xor_sync(~0u, mx, off));
    if ((tid & 31) == 0) red[tid >> 5] = mx;
    __syncthreads();
    mx = -3.0e38f;
    #pragma unroll
    for (int i = 0; i < 8; i++) mx = fmaxf(mx, red[i]);

    float sum = 0.f;
    #pragma unroll
    for (int i = 0; i < 8; i++) {
        int idx = tid + i * 256;
        vals[i] = (idx < nvalid) ? __expf(vals[i] - mx) : 0.f;
        sum += vals[i];
    }
    #pragma unroll
    for (int off = 16; off; off >>= 1) sum += __shfl_xor_sync(~0u, sum, off);
    __syncthreads();
    if ((tid & 31) == 0) red[tid >> 5] = sum;
    __syncthreads();
    float tot = 0.f;
    #pragma unroll
    for (int i = 0; i < 8; i++) tot += red[i];
    float inv = 1.0f / tot;
    #pragma unroll
    for (int i = 0; i < 8; i++) {
        int idx = tid + i * 256;
        row[idx] = to_tf32(vals[i] * inv);
    }
}

// ---------------- launch ----------------
extern "C" void kernel_launch(void* const* d_in, const int* in_sizes, int n_in,
                              void* d_out, int out_size) {
    const float* x   = (const float*)d_in[0];
    const float* anw = (const float*)d_in[1];
    const float* mnw = (const float*)d_in[2];
    const float* wq  = (const float*)d_in[3];
    const float* bq  = (const float*)d_in[4];
    const float* wk  = (const float*)d_in[5];
    const float* bk  = (const float*)d_in[6];
    const float* wv  = (const float*)d_in[7];
    const float* bv  = (const float*)d_in[8];
    const float* wo  = (const float*)d_in[9];
    const float* bo  = (const float*)d_in[10];
    const float* w1  = (const float*)d_in[11];
    const float* b1  = (const float*)d_in[12];
    const float* w2  = (const float*)d_in[13];
    const float* b2  = (const float*)d_in[14];
    float* out = (float*)d_out;

    float *xn, *qkv, *vT, *sc, *attn, *x1, *h, *h1;
    float *wqkvT, *bqkv, *woT, *w1T, *w2T;
    cudaGetSymbolAddress((void**)&xn,    g_xn);
    cudaGetSymbolAddress((void**)&qkv,   g_qkv);
    cudaGetSymbolAddress((void**)&vT,    g_vT);
    cudaGetSymbolAddress((void**)&sc,    g_sc);
    cudaGetSymbolAddress((void**)&attn,  g_attn);
    cudaGetSymbolAddress((void**)&x1,    g_x1);
    cudaGetSymbolAddress((void**)&h,     g_h);
    cudaGetSymbolAddress((void**)&h1,    g_h1);
    cudaGetSymbolAddress((void**)&wqkvT, g_wqkvT);
    cudaGetSymbolAddress((void**)&bqkv,  g_bqkv);
    cudaGetSymbolAddress((void**)&woT,   g_woT);
    cudaGetSymbolAddress((void**)&w1T,   g_w1T);
    cudaGetSymbolAddress((void**)&w2T,   g_w2T);

    cudaFuncSetAttribute(mma_gemm<false,false>, cudaFuncAttributeMaxDynamicSharedMemorySize, SMEM_BYTES);
    cudaFuncSetAttribute(mma_gemm<false,true>,  cudaFuncAttributeMaxDynamicSharedMemorySize, SMEM_BYTES);
    cudaFuncSetAttribute(mma_gemm<true,true>,   cudaFuncAttributeMaxDynamicSharedMemorySize, SMEM_BYTES);

    const long TD  = (long)TLEN * DIM;
    const long T3D = (long)TLEN * 3 * DIM;
    const long TT  = (long)TLEN * TLEN;
    dim3 tb(32, 8);

    // weight transposes (convert to tf32); wq/wk/wv land in one [3072 x 1024] buffer
    transpose_kernel<<<dim3(32, 32), tb>>>(wq, wqkvT,               DIM, DIM, DIM, 0, 0);
    transpose_kernel<<<dim3(32, 32), tb>>>(wk, wqkvT + DIM*DIM,     DIM, DIM, DIM, 0, 0);
    transpose_kernel<<<dim3(32, 32), tb>>>(wv, wqkvT + 2*DIM*DIM,   DIM, DIM, DIM, 0, 0);
    transpose_kernel<<<dim3(32, 32), tb>>>(wo, woT, DIM, DIM, DIM, 0, 0);
    transpose_kernel<<<dim3(128, 32), tb>>>(w1, w1T, DIM, HID, HID, 0, 0);
    transpose_kernel<<<dim3(32, 128), tb>>>(w2, w2T, HID, DIM, DIM, 0, 0);
    concat3_kernel<<<12, 256>>>(bq, bk, bv, bqkv);

    // 1) xn = rmsnorm(x) (tf32)
    rmsnorm_kernel<<<BT, 256>>>(x, anw, xn);

    // 2) qkv = xn @ [wq|wk|wv]^T + bqkv   (M=16384, N=3072, K=1024; tf32 out)
    dim3 gQKV(3 * DIM / 128, BT / 128, 1);
    mma_gemm<false,true><<<gQKV, 256, SMEM_BYTES>>>(xn, wqkvT, qkv, DIM, DIM, DIM, 3*DIM,
                                                    0, 0, 0, 1.f, bqkv, nullptr, 0);
    const float* q = qkv;
    const float* k = qkv + DIM;
    const float* v = qkv + 2 * DIM;

    // v^T per batch: [T,D] (ld 3072) -> [D,T] (tf32)
    transpose_kernel<<<dim3(DIM / 32, TLEN / 32, BATCH), tb>>>(v, vT, TLEN, DIM, 3*DIM, T3D, TD);

    // 3) scores = q @ k^T / 32, causal tiles only
    dim3 gSC(TLEN / 128, TLEN / 128, BATCH);
    mma_gemm<false,false><<<gSC, 256, SMEM_BYTES>>>(q, k, sc, DIM, 3*DIM, 3*DIM, TLEN,
                                                    T3D, T3D, TT, 0.03125f, nullptr, nullptr, 1);

    // 4) causal softmax (probs emitted as tf32)
    softmax_causal_kernel<<<dim3(TLEN, BATCH), 256>>>(sc);

    // 5) attn = probs @ v  (B = vT, K clamped causally; attn emitted tf32)
    dim3 gPV(DIM / 128, TLEN / 128, BATCH);
    mma_gemm<false,true><<<gPV, 256, SMEM_BYTES>>>(sc, vT, attn, TLEN, TLEN, TLEN, DIM,
                                                   TT, TD, TD, 1.f, nullptr, nullptr, 2);

    // 6) x1 = x + attn @ wo^T + bo   (fp32 out)
    dim3 gO(DIM / 128, BT / 128, 1);
    mma_gemm<false,false><<<gO, 256, SMEM_BYTES>>>(attn, woT, x1, DIM, DIM, DIM, DIM,
                                                   0, 0, 0, 1.f, bo, x, 0);

    // 7) h = rmsnorm(x1) (tf32)
    rmsnorm_kernel<<<BT, 256>>>(x1, mnw, h);

    // 8) h1 = gelu(h @ w1^T + b1) (tf32 out)
    dim3 gUP(HID / 128, BT / 128, 1);
    mma_gemm<true,true><<<gUP, 256, SMEM_BYTES>>>(h, w1T, h1, DIM, DIM, DIM, HID,
                                                  0, 0, 0, 1.f, b1, nullptr, 0);

    // 9) out = x1 + h1 @ w2^T + b2 (fp32 out)
    dim3 gDN(DIM / 128, BT / 128, 1);
    mma_gemm<false,false><<<gDN, 256, SMEM_BYTES>>>(h1, w2T, out, HID, HID, HID, DIM,
                                                    0, 0, 0, 1.f, b2, x1, 0);
}